// round 15
// baseline (speedup 1.0000x reference)
#include <cuda_runtime.h>
#include <cuda_bf16.h>
#include <math_constants.h>
#include <cstdint>

#define DD 256        // embedding dim
#define TT 65536      // tokens
#define KK 4096       // codes
#define TM 256        // tokens per CTA
#define TNB 32        // codes per B tile
#define KSPLIT 4      // codebook split across CTAs
#define KHC (KK / KSPLIT)     // 1024 codes per slice
#define NKB (KHC / TNB)       // 32 iterations per CTA

// ---------------- scratch globals (no allocation allowed) ------------------
__device__ __align__(16) __nv_bfloat16 g_Ebf[(size_t)KK * DD]; // codebook bf16
__device__ float  g_C[KK];                // ||e||^2
__device__ float  g_cv[(size_t)TT * 32];  // approx candidates (values)
__device__ int    g_ci[(size_t)TT * 32];  // approx candidates (indices)
__device__ int    g_idx[TT];
__device__ double g_part[TT / 32];

// ---------------- PTX helpers (plain sm_103-compatible) --------------------
__device__ __forceinline__ uint32_t smem_u32(const void* p) {
    uint32_t a;
    asm("{ .reg .u64 t; cvta.to.shared.u64 t, %1; cvt.u32.u64 %0, t; }"
        : "=r"(a) : "l"(p));
    return a;
}
__device__ __forceinline__ void cp16(uint32_t dst, const void* src) {
    asm volatile("cp.async.cg.shared.global [%0], [%1], 16;"
                 :: "r"(dst), "l"(src));
}
__device__ __forceinline__ void cp_commit() {
    asm volatile("cp.async.commit_group;" ::: "memory");
}
template <int N>
__device__ __forceinline__ void cp_wait() {
    asm volatile("cp.async.wait_group %0;" :: "n"(N) : "memory");
}
__device__ __forceinline__ void ldm_x4(uint32_t* r, uint32_t addr) {
    asm volatile("ldmatrix.sync.aligned.m8n8.x4.shared.b16 {%0,%1,%2,%3}, [%4];"
                 : "=r"(r[0]), "=r"(r[1]), "=r"(r[2]), "=r"(r[3]) : "r"(addr));
}
__device__ __forceinline__ void mma16816(float* d, const uint32_t* a,
                                         const uint32_t* b) {
    asm volatile(
        "mma.sync.aligned.m16n8k16.row.col.f32.bf16.bf16.f32 "
        "{%0,%1,%2,%3}, {%4,%5,%6,%7}, {%8,%9}, {%0,%1,%2,%3};"
        : "+f"(d[0]), "+f"(d[1]), "+f"(d[2]), "+f"(d[3])
        : "r"(a[0]), "r"(a[1]), "r"(a[2]), "r"(a[3]), "r"(b[0]), "r"(b[1]));
}
// Swizzled smem tile offset: rows of 512B (256 bf16), XOR-swizzle inside 128B.
__device__ __forceinline__ uint32_t tile_off(int r, int kbyte) {
    return (uint32_t)(r * 512 + (kbyte & ~127) + ((kbyte & 127) ^ ((r & 7) << 4)));
}

// Order-preserving float->uint transform, round-masked, 12-bit idx packed in.
// Perturbation <= 2048 ulps (~1.2e-4); absorbed by the rescore threshold.
__device__ __forceinline__ uint32_t pack_sc(float s, uint32_t c) {
    uint32_t b = __float_as_uint(s);
    uint32_t u = b ^ ((uint32_t)((int32_t)b >> 31) | 0x80000000u);
    return ((u + 0x800u) & 0xFFFFF000u) | c;
}
__device__ __forceinline__ float unpack_val(uint32_t t) {
    uint32_t u = t & 0xFFFFF000u;
    uint32_t b = (u & 0x80000000u) ? (u ^ 0x80000000u) : ~u;
    return __uint_as_float(b);
}

#define SM_A      0                         // 256 rows * 512B = 128 KB (staging)
#define SM_B(p)   (131072 + (p) * 16384)    // 3 x 16 KB B ring
#define SMEM_TOTAL (131072 + 3 * 16384)     // 176 KB

// ---------------------------------------------------------------------------
// Dummy no-op kernel: keeps vq_mma_kernel in ncu's capture slot (4th launch).
// ---------------------------------------------------------------------------
__global__ void nop_kernel() {}

// ---------------------------------------------------------------------------
// Kernel 1: codebook norms + bf16 conversion. One warp per codebook row.
// ---------------------------------------------------------------------------
__global__ void prep_kernel(const float* __restrict__ E, int K)
{
    int row = (int)((blockIdx.x * blockDim.x + threadIdx.x) >> 5);
    int lane = threadIdx.x & 31;
    if (row >= K) return;
    const float4* p = (const float4*)(E + (size_t)row * DD);
    float4 a = p[lane], b = p[lane + 32];
    float s = a.x*a.x + a.y*a.y + a.z*a.z + a.w*a.w
            + b.x*b.x + b.y*b.y + b.z*b.z + b.w*b.w;
    #pragma unroll
    for (int o = 16; o > 0; o >>= 1) s += __shfl_xor_sync(0xffffffffu, s, o);

    __nv_bfloat162* dst = (__nv_bfloat162*)(g_Ebf + (size_t)row * DD);
    dst[2*lane + 0]      = __float22bfloat162_rn(make_float2(a.x, a.y));
    dst[2*lane + 1]      = __float22bfloat162_rn(make_float2(a.z, a.w));
    dst[2*(lane+32) + 0] = __float22bfloat162_rn(make_float2(b.x, b.y));
    dst[2*(lane+32) + 1] = __float22bfloat162_rn(make_float2(b.z, b.w));

    if (lane == 0) g_C[row] = s;
}

// ---------------------------------------------------------------------------
// Kernel 2: bf16 HMMA GEMM (z @ E^T) + per-token packed top-2 per lane-col.
// K-split grid (1024 CTAs), 8 warps x 32 rows, 3-stage cp.async B ring,
// one barrier/iter. NEW: DOUBLE-BUFFERED ACCUMULATORS + DEFERRED EPILOGUE —
// the epilogue for tile kb-1 (reading acc[prev], no dependency on in-flight
// MMAs) issues on the ALU/FMA pipes while the tensor pipe drains tile kb's
// HMMAs, removing the drain-then-score serialization. To fit registers,
// A k-steps 0-7 stay resident; 8-15 are ldsm'd per iter (crossbar 1536
// cyc/iter, still under the 2048-cyc tensor floor).
// ---------------------------------------------------------------------------
#define EPILOGUE(buf, kbp) do {                                                \
    const uint32_t cbE = (uint32_t)(code0 + (kbp) * TNB + (l & 3) * 2);        \
    _Pragma("unroll")                                                          \
    for (int mi = 0; mi < 2; mi++) {                                           \
        _Pragma("unroll")                                                      \
        for (int half = 0; half < 2; half++) {                                 \
            const int q = mi * 2 + half;                                       \
            uint32_t r0 = t0[q], r1 = t1[q];                                   \
            _Pragma("unroll")                                                  \
            for (int ni = 0; ni < 4; ni++) {                                   \
                float s0 = fmaf(-2.f, acc[buf][mi][ni][half*2+0], Cv[buf][ni].x); \
                float s1 = fmaf(-2.f, acc[buf][mi][ni][half*2+1], Cv[buf][ni].y); \
                uint32_t p0 = pack_sc(s0, cbE + (uint32_t)(ni * 8));           \
                uint32_t p1 = pack_sc(s1, cbE + (uint32_t)(ni * 8) + 1u);      \
                uint32_t lo = umin(p0, p1), hi = umax(p0, p1);                 \
                uint32_t n1 = umin(umax(r0, lo), umin(r1, hi));                \
                r0 = umin(r0, lo);                                             \
                r1 = n1;                                                       \
            }                                                                  \
            t0[q] = r0; t1[q] = r1;                                            \
        }                                                                      \
    }                                                                          \
} while (0)

__global__ __launch_bounds__(256, 1) void vq_mma_kernel(const float* __restrict__ z)
{
    extern __shared__ char smem[];
    const uint32_t sa = smem_u32(smem);
    const int tid = threadIdx.x;
    const int tile = blockIdx.x >> 2;        // token tile
    const int kh   = blockIdx.x & 3;         // codebook slice
    const int row0 = tile * TM;
    const int code0 = kh * KHC;

    // ---- B tile 0 via cp.async (overlaps with A staging below) ----
    {
        const char* srcB = (const char*)g_Ebf + (size_t)code0 * 512;
        #pragma unroll
        for (int i = 0; i < 4; i++) {          // 32 rows x 32 chunks / 256 thr
            int idx = i * 256 + tid;
            int r = idx >> 5, c = idx & 31;
            cp16(sa + SM_B(0) + tile_off(r, c * 16), srcB + (size_t)r * 512 + c * 16);
        }
        cp_commit();
    }

    // ---- stage A: read fp32 z, convert to bf16 into swizzled smem ----
    {
        const float4* srcZ = (const float4*)(z + (size_t)row0 * DD);
        #pragma unroll
        for (int i = 0; i < 64; i++) {         // 256 rows x 64 float4 / 256 thr
            int idx = i * 256 + tid;
            int r = idx >> 6, c = idx & 63;    // c: float4 index within row
            float4 f = srcZ[(size_t)r * 64 + c];
            __nv_bfloat162 h0 = __float22bfloat162_rn(make_float2(f.x, f.y));
            __nv_bfloat162 h1 = __float22bfloat162_rn(make_float2(f.z, f.w));
            uint2 v = make_uint2(*reinterpret_cast<uint32_t*>(&h0),
                                 *reinterpret_cast<uint32_t*>(&h1));
            *(uint2*)(smem + SM_A + tile_off(r, c * 8)) = v;
        }
    }
    __syncthreads();

    const int l = tid & 31, w = tid >> 5;     // 8 warps, 32 rows each

    // ---- load A fragments for k-steps 0..7 into registers (once) ----
    const int a_r  = l & 15;
    const int a_kb = (l >> 4) * 16;
    uint32_t afr[2][8][4];
    #pragma unroll
    for (int mi = 0; mi < 2; mi++)
        #pragma unroll
        for (int ks = 0; ks < 8; ks++)
            ldm_x4(afr[mi][ks],
                   sa + SM_A + tile_off(w * 32 + mi * 16 + a_r, ks * 32 + a_kb));

    uint32_t t0[4], t1[4];                    // packed top-2 per lane-col
    #pragma unroll
    for (int q = 0; q < 4; q++) { t0[q] = 0xFFFFFFFFu; t1[q] = 0xFFFFFFFFu; }

    const int b_r  = ((l >> 4) << 3) + (l & 7);
    const int b_kb = ((l >> 3) & 1) * 16;

    float  acc[2][2][4][4];                   // [buffer][mi][ni][j]
    float2 Cv[2][4];                          // [buffer][ni]

    int ridx = 0;                 // ring stage holding tile kb
    for (int kb = 0; kb < NKB; kb++) {
        if (kb < NKB - 1) {   // prefetch next B tile into ring[(ridx+1)%3]
            const char* srcB = (const char*)g_Ebf
                             + (size_t)(code0 + (kb + 1) * TNB) * 512;
            int pidx = (ridx == 2) ? 0 : ridx + 1;
            uint32_t db = sa + SM_B(pidx);
            #pragma unroll
            for (int i = 0; i < 4; i++) {
                int idx = i * 256 + tid;
                int r = idx >> 5, c = idx & 31;
                cp16(db + tile_off(r, c * 16), srcB + (size_t)r * 512 + c * 16);
            }
            cp_commit();
            cp_wait<1>();    // tile kb complete (only kb+1 may remain pending)
        } else {
            cp_wait<0>();
        }
        // Single barrier: tile kb visible; prefetch target (last read kb-2)
        // cannot race any reader (reuse distance 3).
        __syncthreads();

        const uint32_t sB = sa + SM_B(ridx);
        ridx = (ridx == 2) ? 0 : ridx + 1;

        const int cur = kb & 1, prv = cur ^ 1;

        // prefetch C for this tile into Cv[cur] (hidden under MMA phase)
        #pragma unroll
        for (int ni = 0; ni < 4; ni++)
            Cv[cur][ni] = __ldg((const float2*)(g_C + code0 + kb * TNB + ni * 8
                                                + (l & 3) * 2));

        #pragma unroll
        for (int mi = 0; mi < 2; mi++)
            #pragma unroll
            for (int ni = 0; ni < 4; ni++)
                #pragma unroll
                for (int j = 0; j < 4; j++) acc[cur][mi][ni][j] = 0.f;

        #pragma unroll
        for (int ks = 0; ks < 16; ks++) {
            const int k0b = ks * 32;
            uint32_t bfrag[4][2];
            #pragma unroll
            for (int nj = 0; nj < 2; nj++) {
                uint32_t t4[4];
                ldm_x4(t4, sB + tile_off(nj * 16 + b_r, k0b + b_kb));
                bfrag[2*nj][0]   = t4[0]; bfrag[2*nj][1]   = t4[1];
                bfrag[2*nj+1][0] = t4[2]; bfrag[2*nj+1][1] = t4[3];
            }
            uint32_t a0[4], a1[4];
            const uint32_t *ap0, *ap1;
            if (ks < 8) { ap0 = afr[0][ks]; ap1 = afr[1][ks]; }
            else {
                ldm_x4(a0, sa + SM_A + tile_off(w * 32 + a_r,      k0b + a_kb));
                ldm_x4(a1, sa + SM_A + tile_off(w * 32 + 16 + a_r, k0b + a_kb));
                ap0 = a0; ap1 = a1;
            }
            #pragma unroll
            for (int ni = 0; ni < 4; ni++) {
                mma16816(acc[cur][0][ni], ap0, bfrag[ni]);
                mma16816(acc[cur][1][ni], ap1, bfrag[ni]);
            }
        }

        // ---- DEFERRED epilogue for tile kb-1: reads acc[prv] (already
        // drained), issues on alu/fma while the tensor pipe drains tile kb.
        if (kb > 0) EPILOGUE(prv, kb - 1);
    }
    EPILOGUE((NKB - 1) & 1, NKB - 1);         // final tile's epilogue

    // write 8 candidates per token into this slice's section (of 32)
    #pragma unroll
    for (int q = 0; q < 4; q++) {
        const int mi = q >> 1, half = q & 1;
        const int r = row0 + w * 32 + mi * 16 + (l >> 2) + half * 8;
        const int base = r * 32 + kh * 8 + (l & 3) * 2;
        g_cv[base]     = unpack_val(t0[q]);
        g_cv[base + 1] = unpack_val(t1[q]);
        g_ci[base]     = (int)(t0[q] & 0xFFFu);
        g_ci[base + 1] = (int)(t1[q] & 0xFFFu);
    }
}

// ---------------------------------------------------------------------------
// Kernel 3: exact rescore of near-tie candidates (reference rounding
// fl(fl(A - 2m) + C), lowest-index tie-break). One warp per token,
// 32 candidates (8 per codebook slice).
// Threshold 4e-4 = bf16 filter noise (1.5e-4) + 2x packing slop (1.2e-4).
// ---------------------------------------------------------------------------
__global__ void rescore_kernel(const float* __restrict__ z,
                               const float* __restrict__ E, int T)
{
    int warp = (int)((blockIdx.x * blockDim.x + threadIdx.x) >> 5);
    int lane = threadIdx.x & 31;
    if (warp >= T) return;
    const size_t t = (size_t)warp;

    float vL = g_cv[t * 32 + lane];
    int   iL = g_ci[t * 32 + lane];
    float v0 = vL;
    #pragma unroll
    for (int o = 16; o > 0; o >>= 1)
        v0 = fminf(v0, __shfl_xor_sync(0xffffffffu, v0, o));
    const float thr = v0 + 4e-4f;
    unsigned mask = __ballot_sync(0xffffffffu, vL <= thr);

    int besti;
    if (__popc(mask) == 1) {
        besti = __shfl_sync(0xffffffffu, iL, __ffs(mask) - 1);
    } else {
        const float4* zp = (const float4*)(z + t * DD);
        float4 z0 = zp[lane], z1 = zp[lane + 32];
        float A = z0.x*z0.x + z0.y*z0.y + z0.z*z0.z + z0.w*z0.w
                + z1.x*z1.x + z1.y*z1.y + z1.z*z1.z + z1.w*z1.w;
        #pragma unroll
        for (int o = 16; o > 0; o >>= 1)
            A += __shfl_xor_sync(0xffffffffu, A, o);

        float bd = CUDART_INF_F; besti = 0x7fffffff;
        #pragma unroll 1
        for (int c = 0; c < 32; c++) {
            if (!((mask >> c) & 1u)) continue;
            int ic = __shfl_sync(0xffffffffu, iL, c);
            const float4* ep = (const float4*)(E + (size_t)ic * DD);
            float4 e0 = ep[lane], e1 = ep[lane + 32];
            float pm = z0.x*e0.x + z0.y*e0.y + z0.z*e0.z + z0.w*e0.w
                     + z1.x*e1.x + z1.y*e1.y + z1.z*e1.z + z1.w*e1.w;
            #pragma unroll
            for (int o = 16; o > 0; o >>= 1)
                pm += __shfl_xor_sync(0xffffffffu, pm, o);
            float d = fmaf(-2.0f, pm, A) + g_C[ic];
            if (d < bd || (d == bd && ic < besti)) { bd = d; besti = ic; }
        }
    }
    if (lane == 0) g_idx[t] = besti;
}

// ---------------------------------------------------------------------------
// Kernel 4: gather quantized rows (float4), write indices, loss partials.
// Per-thread fp32 accumulation (32 terms); block reduction in double.
// ---------------------------------------------------------------------------
__global__ void vq_gather_kernel(const float* __restrict__ z,
                                 const float* __restrict__ E,
                                 float* __restrict__ out,
                                 int T, int with_idx)
{
    __shared__ double sred[256];
    const int tid = threadIdx.x;
    const int cg = tid & 63;       // float4 column group
    const int ro = tid >> 6;       // row offset 0..3
    const int rbase = blockIdx.x * 32;
    const float4* z4 = (const float4*)z;
    const float4* E4 = (const float4*)E;
    float4* out4 = (float4*)out;

    float acc = 0.0f;
    #pragma unroll
    for (int rr = 0; rr < 8; rr++) {
        int row = rbase + rr * 4 + ro;
        int k = g_idx[row];
        float4 e  = __ldg(E4 + (size_t)k * 64 + cg);
        float4 zv = __ldg(z4 + (size_t)row * 64 + cg);
        out4[(size_t)row * 64 + cg] = e;
        float d0 = e.x - zv.x, d1 = e.y - zv.y;
        float d2 = e.z - zv.z, d3 = e.w - zv.w;
        acc = fmaf(d0, d0, acc); acc = fmaf(d1, d1, acc);
        acc = fmaf(d2, d2, acc); acc = fmaf(d3, d3, acc);
        if (with_idx && cg == 0) out[(size_t)T * DD + row] = (float)k;
    }
    sred[tid] = (double)acc;
    __syncthreads();
    #pragma unroll
    for (int o = 128; o > 0; o >>= 1) {
        if (tid < o) sred[tid] += sred[tid + o];
        __syncthreads();
    }
    if (tid == 0) g_part[blockIdx.x] = sred[0];
}

__global__ void vq_loss_kernel(float* __restrict__ out, int T, int npart)
{
    __shared__ double sred[256];
    int tid = threadIdx.x;
    double acc = 0.0;
    for (int i = tid; i < npart; i += 256) acc += g_part[i];
    sred[tid] = acc;
    __syncthreads();
    #pragma unroll
    for (int o = 128; o > 0; o >>= 1) {
        if (tid < o) sred[tid] += sred[tid + o];
        __syncthreads();
    }
    if (tid == 0) {
        float m = (float)(sred[0] / ((double)T * (double)DD));
        out[(size_t)T * DD + T] = m + 0.25f * m;
    }
}

// ---------------------------------------------------------------------------
extern "C" void kernel_launch(void* const* d_in, const int* in_sizes, int n_in,
                              void* d_out, int out_size)
{
    const float* z = (const float*)d_in[0];
    const float* E = (const float*)d_in[1];
    float* out = (float*)d_out;

    int T = in_sizes[0] / DD;   // 65536
    int K = in_sizes[1] / DD;   // 4096

    prep_kernel<<<(K * 32 + 255) / 256, 256>>>(E, K);

    // slot-alignment dummies: keep vq_mma_kernel in ncu's 4th-launch slot
    nop_kernel<<<1, 32>>>();
    nop_kernel<<<1, 32>>>();

    cudaFuncSetAttribute(vq_mma_kernel,
                         cudaFuncAttributeMaxDynamicSharedMemorySize, SMEM_TOTAL);
    vq_mma_kernel<<<(T / TM) * KSPLIT, 256, SMEM_TOTAL>>>(z);

    rescore_kernel<<<T / 8, 256>>>(z, E, T);

    long long need_idx = (long long)T * DD + T;
    int with_idx = (out_size >= need_idx) ? 1 : 0;
    vq_gather_kernel<<<T / 32, 256>>>(z, E, out, T, with_idx);

    if (out_size >= need_idx + 1)
        vq_loss_kernel<<<1, 256>>>(out, T, T / 32);
}

// round 16
// speedup vs baseline: 1.4274x; 1.4274x over previous
#include <cuda_runtime.h>
#include <cuda_bf16.h>
#include <math_constants.h>
#include <cstdint>

#define DD 256        // embedding dim
#define TT 65536      // tokens
#define KK 4096       // codes
#define TM 256        // tokens per CTA
#define TNB 64        // codes per B tile (doubled: halves per-iter fixed costs)
#define KSPLIT 4      // codebook split across CTAs
#define KHC (KK / KSPLIT)     // 1024 codes per slice
#define NKB (KHC / TNB)       // 16 iterations per CTA

// ---------------- scratch globals (no allocation allowed) ------------------
__device__ __align__(16) __nv_bfloat16 g_Ebf[(size_t)KK * DD]; // codebook bf16
__device__ float  g_C[KK];                // ||e||^2
__device__ float  g_cv[(size_t)TT * 32];  // approx candidates (values)
__device__ int    g_ci[(size_t)TT * 32];  // approx candidates (indices)
__device__ int    g_idx[TT];
__device__ double g_part[TT / 32];

// ---------------- PTX helpers (plain sm_103-compatible) --------------------
__device__ __forceinline__ uint32_t smem_u32(const void* p) {
    uint32_t a;
    asm("{ .reg .u64 t; cvta.to.shared.u64 t, %1; cvt.u32.u64 %0, t; }"
        : "=r"(a) : "l"(p));
    return a;
}
__device__ __forceinline__ void cp16(uint32_t dst, const void* src) {
    asm volatile("cp.async.cg.shared.global [%0], [%1], 16;"
                 :: "r"(dst), "l"(src));
}
__device__ __forceinline__ void cp_commit() {
    asm volatile("cp.async.commit_group;" ::: "memory");
}
template <int N>
__device__ __forceinline__ void cp_wait() {
    asm volatile("cp.async.wait_group %0;" :: "n"(N) : "memory");
}
__device__ __forceinline__ void ldm_x4(uint32_t* r, uint32_t addr) {
    asm volatile("ldmatrix.sync.aligned.m8n8.x4.shared.b16 {%0,%1,%2,%3}, [%4];"
                 : "=r"(r[0]), "=r"(r[1]), "=r"(r[2]), "=r"(r[3]) : "r"(addr));
}
__device__ __forceinline__ void mma16816(float* d, const uint32_t* a,
                                         const uint32_t* b) {
    asm volatile(
        "mma.sync.aligned.m16n8k16.row.col.f32.bf16.bf16.f32 "
        "{%0,%1,%2,%3}, {%4,%5,%6,%7}, {%8,%9}, {%0,%1,%2,%3};"
        : "+f"(d[0]), "+f"(d[1]), "+f"(d[2]), "+f"(d[3])
        : "r"(a[0]), "r"(a[1]), "r"(a[2]), "r"(a[3]), "r"(b[0]), "r"(b[1]));
}
// Swizzled smem tile offset: rows of 512B (256 bf16), XOR-swizzle inside 128B.
__device__ __forceinline__ uint32_t tile_off(int r, int kbyte) {
    return (uint32_t)(r * 512 + (kbyte & ~127) + ((kbyte & 127) ^ ((r & 7) << 4)));
}

// Order-preserving float->uint transform, round-masked, 12-bit idx packed in.
// Perturbation <= 2048 ulps (~1.2e-4); absorbed by the rescore threshold.
__device__ __forceinline__ uint32_t pack_sc(float s, uint32_t c) {
    uint32_t b = __float_as_uint(s);
    uint32_t u = b ^ ((uint32_t)((int32_t)b >> 31) | 0x80000000u);
    return ((u + 0x800u) & 0xFFFFF000u) | c;
}
__device__ __forceinline__ float unpack_val(uint32_t t) {
    uint32_t u = t & 0xFFFFF000u;
    uint32_t b = (u & 0x80000000u) ? (u ^ 0x80000000u) : ~u;
    return __uint_as_float(b);
}

#define SM_A      0                         // 256 rows * 512B = 128 KB (staging)
#define SM_B(p)   (131072 + (p) * 32768)    // 3 x 32 KB B ring
#define SMEM_TOTAL (131072 + 3 * 32768)     // 224 KB

// ---------------------------------------------------------------------------
// Dummy no-op kernel: keeps vq_mma_kernel in ncu's capture slot (4th launch).
// ---------------------------------------------------------------------------
__global__ void nop_kernel() {}

// ---------------------------------------------------------------------------
// Kernel 1: codebook norms + bf16 conversion. One warp per codebook row.
// ---------------------------------------------------------------------------
__global__ void prep_kernel(const float* __restrict__ E, int K)
{
    int row = (int)((blockIdx.x * blockDim.x + threadIdx.x) >> 5);
    int lane = threadIdx.x & 31;
    if (row >= K) return;
    const float4* p = (const float4*)(E + (size_t)row * DD);
    float4 a = p[lane], b = p[lane + 32];
    float s = a.x*a.x + a.y*a.y + a.z*a.z + a.w*a.w
            + b.x*b.x + b.y*b.y + b.z*b.z + b.w*b.w;
    #pragma unroll
    for (int o = 16; o > 0; o >>= 1) s += __shfl_xor_sync(0xffffffffu, s, o);

    __nv_bfloat162* dst = (__nv_bfloat162*)(g_Ebf + (size_t)row * DD);
    dst[2*lane + 0]      = __float22bfloat162_rn(make_float2(a.x, a.y));
    dst[2*lane + 1]      = __float22bfloat162_rn(make_float2(a.z, a.w));
    dst[2*(lane+32) + 0] = __float22bfloat162_rn(make_float2(b.x, b.y));
    dst[2*(lane+32) + 1] = __float22bfloat162_rn(make_float2(b.z, b.w));

    if (lane == 0) g_C[row] = s;
}

// ---------------------------------------------------------------------------
// Kernel 2: bf16 HMMA GEMM (z @ E^T) + per-token packed top-2 per lane-col.
// K-split grid (1024 CTAs), 8 warps x 32 rows. TNB=64: per-iter tensor work
// doubles to 4096 cyc/SMSP, so the fixed per-iter costs (barrier, cp_wait,
// end-of-loop epilogue serialization) amortize over 2x the work and the
// barrier count halves (16 iters). Registers stay ~210 (acc 64 single-
// buffered, afr only ks 0-3 resident = 32; ks 4-15 ldsm'd per iter, which
// still leaves LDS 2816 cyc < 4096 tensor floor).
// ---------------------------------------------------------------------------
__global__ __launch_bounds__(256, 1) void vq_mma_kernel(const float* __restrict__ z)
{
    extern __shared__ char smem[];
    const uint32_t sa = smem_u32(smem);
    const int tid = threadIdx.x;
    const int tile = blockIdx.x >> 2;        // token tile
    const int kh   = blockIdx.x & 3;         // codebook slice
    const int row0 = tile * TM;
    const int code0 = kh * KHC;

    // ---- B tile 0 via cp.async (overlaps with A staging below) ----
    {
        const char* srcB = (const char*)g_Ebf + (size_t)code0 * 512;
        #pragma unroll
        for (int i = 0; i < 8; i++) {          // 64 rows x 32 chunks / 256 thr
            int idx = i * 256 + tid;
            int r = idx >> 5, c = idx & 31;
            cp16(sa + SM_B(0) + tile_off(r, c * 16), srcB + (size_t)r * 512 + c * 16);
        }
        cp_commit();
    }

    // ---- stage A: read fp32 z, convert to bf16 into swizzled smem ----
    {
        const float4* srcZ = (const float4*)(z + (size_t)row0 * DD);
        #pragma unroll
        for (int i = 0; i < 64; i++) {         // 256 rows x 64 float4 / 256 thr
            int idx = i * 256 + tid;
            int r = idx >> 6, c = idx & 63;    // c: float4 index within row
            float4 f = srcZ[(size_t)r * 64 + c];
            __nv_bfloat162 h0 = __float22bfloat162_rn(make_float2(f.x, f.y));
            __nv_bfloat162 h1 = __float22bfloat162_rn(make_float2(f.z, f.w));
            uint2 v = make_uint2(*reinterpret_cast<uint32_t*>(&h0),
                                 *reinterpret_cast<uint32_t*>(&h1));
            *(uint2*)(smem + SM_A + tile_off(r, c * 8)) = v;
        }
    }
    __syncthreads();

    const int l = tid & 31, w = tid >> 5;     // 8 warps, 32 rows each

    // ---- load A fragments for k-steps 0..3 into registers (once) ----
    const int a_r  = l & 15;
    const int a_kb = (l >> 4) * 16;
    uint32_t afr[2][4][4];
    #pragma unroll
    for (int mi = 0; mi < 2; mi++)
        #pragma unroll
        for (int ks = 0; ks < 4; ks++)
            ldm_x4(afr[mi][ks],
                   sa + SM_A + tile_off(w * 32 + mi * 16 + a_r, ks * 32 + a_kb));

    uint32_t t0[4], t1[4];                    // packed top-2 per lane-col
    #pragma unroll
    for (int q = 0; q < 4; q++) { t0[q] = 0xFFFFFFFFu; t1[q] = 0xFFFFFFFFu; }

    const int b_r  = ((l >> 4) << 3) + (l & 7);
    const int b_kb = ((l >> 3) & 1) * 16;

    float acc[2][8][4];                       // [mi][ni][j]

    int ridx = 0;                 // ring stage holding tile kb
    for (int kb = 0; kb < NKB; kb++) {
        if (kb < NKB - 1) {   // prefetch next B tile into ring[(ridx+1)%3]
            const char* srcB = (const char*)g_Ebf
                             + (size_t)(code0 + (kb + 1) * TNB) * 512;
            int pidx = (ridx == 2) ? 0 : ridx + 1;
            uint32_t db = sa + SM_B(pidx);
            #pragma unroll
            for (int i = 0; i < 8; i++) {
                int idx = i * 256 + tid;
                int r = idx >> 5, c = idx & 31;
                cp16(db + tile_off(r, c * 16), srcB + (size_t)r * 512 + c * 16);
            }
            cp_commit();
            cp_wait<1>();    // tile kb complete (only kb+1 may remain pending)
        } else {
            cp_wait<0>();
        }
        // Single barrier: tile kb visible; prefetch target (last read kb-2)
        // cannot race any reader (reuse distance 3).
        __syncthreads();

        const uint32_t sB = sa + SM_B(ridx);
        ridx = (ridx == 2) ? 0 : ridx + 1;

        // prefetch C for this tile (latency hidden under the MMA phase)
        float2 Cv[8];
        #pragma unroll
        for (int ni = 0; ni < 8; ni++)
            Cv[ni] = __ldg((const float2*)(g_C + code0 + kb * TNB + ni * 8
                                           + (l & 3) * 2));

        #pragma unroll
        for (int mi = 0; mi < 2; mi++)
            #pragma unroll
            for (int ni = 0; ni < 8; ni++)
                #pragma unroll
                for (int j = 0; j < 4; j++) acc[mi][ni][j] = 0.f;

        #pragma unroll
        for (int ks = 0; ks < 16; ks++) {
            const int k0b = ks * 32;
            uint32_t bfrag[8][2];
            #pragma unroll
            for (int nj = 0; nj < 4; nj++) {
                uint32_t t4[4];
                ldm_x4(t4, sB + tile_off(nj * 16 + b_r, k0b + b_kb));
                bfrag[2*nj][0]   = t4[0]; bfrag[2*nj][1]   = t4[1];
                bfrag[2*nj+1][0] = t4[2]; bfrag[2*nj+1][1] = t4[3];
            }
            uint32_t a0[4], a1[4];
            const uint32_t *ap0, *ap1;
            if (ks < 4) { ap0 = afr[0][ks]; ap1 = afr[1][ks]; }
            else {
                ldm_x4(a0, sa + SM_A + tile_off(w * 32 + a_r,      k0b + a_kb));
                ldm_x4(a1, sa + SM_A + tile_off(w * 32 + 16 + a_r, k0b + a_kb));
                ap0 = a0; ap1 = a1;
            }
            #pragma unroll
            for (int ni = 0; ni < 8; ni++) {
                mma16816(acc[0][ni], ap0, bfrag[ni]);
                mma16816(acc[1][ni], ap1, bfrag[ni]);
            }
        }

        // ---- epilogue: packed branch-free top-2 (bitonic merges) ----
        const uint32_t cb = (uint32_t)(code0 + kb * TNB + (l & 3) * 2);
        #pragma unroll
        for (int mi = 0; mi < 2; mi++) {
            #pragma unroll
            for (int half = 0; half < 2; half++) {
                const int q = mi * 2 + half;
                uint32_t r0 = t0[q], r1 = t1[q];
                #pragma unroll
                for (int ni = 0; ni < 8; ni++) {
                    float s0 = fmaf(-2.f, acc[mi][ni][half * 2 + 0], Cv[ni].x);
                    float s1 = fmaf(-2.f, acc[mi][ni][half * 2 + 1], Cv[ni].y);
                    uint32_t p0 = pack_sc(s0, cb + (uint32_t)(ni * 8));
                    uint32_t p1 = pack_sc(s1, cb + (uint32_t)(ni * 8) + 1u);
                    uint32_t lo = umin(p0, p1), hi = umax(p0, p1);
                    uint32_t n1 = umin(umax(r0, lo), umin(r1, hi));
                    r0 = umin(r0, lo);
                    r1 = n1;
                }
                t0[q] = r0; t1[q] = r1;
            }
        }
        // no trailing barrier: 3-stage ring gives reuse distance 3
    }

    // write 8 candidates per token into this slice's section (of 32)
    #pragma unroll
    for (int q = 0; q < 4; q++) {
        const int mi = q >> 1, half = q & 1;
        const int r = row0 + w * 32 + mi * 16 + (l >> 2) + half * 8;
        const int base = r * 32 + kh * 8 + (l & 3) * 2;
        g_cv[base]     = unpack_val(t0[q]);
        g_cv[base + 1] = unpack_val(t1[q]);
        g_ci[base]     = (int)(t0[q] & 0xFFFu);
        g_ci[base + 1] = (int)(t1[q] & 0xFFFu);
    }
}

// ---------------------------------------------------------------------------
// Kernel 3: exact rescore of near-tie candidates (reference rounding
// fl(fl(A - 2m) + C), lowest-index tie-break). One warp per token,
// 32 candidates (8 per codebook slice).
// Threshold 4e-4 = bf16 filter noise (1.5e-4) + 2x packing slop (1.2e-4).
// ---------------------------------------------------------------------------
__global__ void rescore_kernel(const float* __restrict__ z,
                               const float* __restrict__ E, int T)
{
    int warp = (int)((blockIdx.x * blockDim.x + threadIdx.x) >> 5);
    int lane = threadIdx.x & 31;
    if (warp >= T) return;
    const size_t t = (size_t)warp;

    float vL = g_cv[t * 32 + lane];
    int   iL = g_ci[t * 32 + lane];
    float v0 = vL;
    #pragma unroll
    for (int o = 16; o > 0; o >>= 1)
        v0 = fminf(v0, __shfl_xor_sync(0xffffffffu, v0, o));
    const float thr = v0 + 4e-4f;
    unsigned mask = __ballot_sync(0xffffffffu, vL <= thr);

    int besti;
    if (__popc(mask) == 1) {
        besti = __shfl_sync(0xffffffffu, iL, __ffs(mask) - 1);
    } else {
        const float4* zp = (const float4*)(z + t * DD);
        float4 z0 = zp[lane], z1 = zp[lane + 32];
        float A = z0.x*z0.x + z0.y*z0.y + z0.z*z0.z + z0.w*z0.w
                + z1.x*z1.x + z1.y*z1.y + z1.z*z1.z + z1.w*z1.w;
        #pragma unroll
        for (int o = 16; o > 0; o >>= 1)
            A += __shfl_xor_sync(0xffffffffu, A, o);

        float bd = CUDART_INF_F; besti = 0x7fffffff;
        #pragma unroll 1
        for (int c = 0; c < 32; c++) {
            if (!((mask >> c) & 1u)) continue;
            int ic = __shfl_sync(0xffffffffu, iL, c);
            const float4* ep = (const float4*)(E + (size_t)ic * DD);
            float4 e0 = ep[lane], e1 = ep[lane + 32];
            float pm = z0.x*e0.x + z0.y*e0.y + z0.z*e0.z + z0.w*e0.w
                     + z1.x*e1.x + z1.y*e1.y + z1.z*e1.z + z1.w*e1.w;
            #pragma unroll
            for (int o = 16; o > 0; o >>= 1)
                pm += __shfl_xor_sync(0xffffffffu, pm, o);
            float d = fmaf(-2.0f, pm, A) + g_C[ic];
            if (d < bd || (d == bd && ic < besti)) { bd = d; besti = ic; }
        }
    }
    if (lane == 0) g_idx[t] = besti;
}

// ---------------------------------------------------------------------------
// Kernel 4: gather quantized rows (float4), write indices, loss partials.
// Per-thread fp32 accumulation (32 terms); block reduction in double.
// ---------------------------------------------------------------------------
__global__ void vq_gather_kernel(const float* __restrict__ z,
                                 const float* __restrict__ E,
                                 float* __restrict__ out,
                                 int T, int with_idx)
{
    __shared__ double sred[256];
    const int tid = threadIdx.x;
    const int cg = tid & 63;       // float4 column group
    const int ro = tid >> 6;       // row offset 0..3
    const int rbase = blockIdx.x * 32;
    const float4* z4 = (const float4*)z;
    const float4* E4 = (const float4*)E;
    float4* out4 = (float4*)out;

    float acc = 0.0f;
    #pragma unroll
    for (int rr = 0; rr < 8; rr++) {
        int row = rbase + rr * 4 + ro;
        int k = g_idx[row];
        float4 e  = __ldg(E4 + (size_t)k * 64 + cg);
        float4 zv = __ldg(z4 + (size_t)row * 64 + cg);
        out4[(size_t)row * 64 + cg] = e;
        float d0 = e.x - zv.x, d1 = e.y - zv.y;
        float d2 = e.z - zv.z, d3 = e.w - zv.w;
        acc = fmaf(d0, d0, acc); acc = fmaf(d1, d1, acc);
        acc = fmaf(d2, d2, acc); acc = fmaf(d3, d3, acc);
        if (with_idx && cg == 0) out[(size_t)T * DD + row] = (float)k;
    }
    sred[tid] = (double)acc;
    __syncthreads();
    #pragma unroll
    for (int o = 128; o > 0; o >>= 1) {
        if (tid < o) sred[tid] += sred[tid + o];
        __syncthreads();
    }
    if (tid == 0) g_part[blockIdx.x] = sred[0];
}

__global__ void vq_loss_kernel(float* __restrict__ out, int T, int npart)
{
    __shared__ double sred[256];
    int tid = threadIdx.x;
    double acc = 0.0;
    for (int i = tid; i < npart; i += 256) acc += g_part[i];
    sred[tid] = acc;
    __syncthreads();
    #pragma unroll
    for (int o = 128; o > 0; o >>= 1) {
        if (tid < o) sred[tid] += sred[tid + o];
        __syncthreads();
    }
    if (tid == 0) {
        float m = (float)(sred[0] / ((double)T * (double)DD));
        out[(size_t)T * DD + T] = m + 0.25f * m;
    }
}

// ---------------------------------------------------------------------------
extern "C" void kernel_launch(void* const* d_in, const int* in_sizes, int n_in,
                              void* d_out, int out_size)
{
    const float* z = (const float*)d_in[0];
    const float* E = (const float*)d_in[1];
    float* out = (float*)d_out;

    int T = in_sizes[0] / DD;   // 65536
    int K = in_sizes[1] / DD;   // 4096

    prep_kernel<<<(K * 32 + 255) / 256, 256>>>(E, K);

    // slot-alignment dummies: keep vq_mma_kernel in ncu's 4th-launch slot
    nop_kernel<<<1, 32>>>();
    nop_kernel<<<1, 32>>>();

    cudaFuncSetAttribute(vq_mma_kernel,
                         cudaFuncAttributeMaxDynamicSharedMemorySize, SMEM_TOTAL);
    vq_mma_kernel<<<(T / TM) * KSPLIT, 256, SMEM_TOTAL>>>(z);

    rescore_kernel<<<T / 8, 256>>>(z, E, T);

    long long need_idx = (long long)T * DD + T;
    int with_idx = (out_size >= need_idx) ? 1 : 0;
    vq_gather_kernel<<<T / 32, 256>>>(z, E, out, T, with_idx);

    if (out_size >= need_idx + 1)
        vq_loss_kernel<<<1, 256>>>(out, T, T / 32);
}

// round 17
// speedup vs baseline: 1.4674x; 1.0280x over previous
#include <cuda_runtime.h>
#include <cuda_bf16.h>
#include <math_constants.h>
#include <cstdint>

#define DD 256        // embedding dim
#define TT 65536      // tokens
#define KK 4096       // codes
#define TM 256        // tokens per CTA
#define TNB 32        // codes per B tile
#define KSPLIT 4      // codebook split across CTAs
#define KHC (KK / KSPLIT)     // 1024 codes per slice
#define NKB (KHC / TNB)       // 32 iterations per CTA

// ---------------- scratch globals (no allocation allowed) ------------------
__device__ __align__(16) __nv_bfloat16 g_Ebf[(size_t)KK * DD]; // codebook bf16
__device__ float  g_C[KK];                // ||e||^2
__device__ float  g_cv[(size_t)TT * 32];  // approx candidates (values)
__device__ int    g_ci[(size_t)TT * 32];  // approx candidates (indices)
__device__ int    g_idx[TT];
__device__ double g_part[TT / 32];

// ---------------- PTX helpers (plain sm_103-compatible) --------------------
__device__ __forceinline__ uint32_t smem_u32(const void* p) {
    uint32_t a;
    asm("{ .reg .u64 t; cvta.to.shared.u64 t, %1; cvt.u32.u64 %0, t; }"
        : "=r"(a) : "l"(p));
    return a;
}
__device__ __forceinline__ void cp16(uint32_t dst, const void* src) {
    asm volatile("cp.async.cg.shared.global [%0], [%1], 16;"
                 :: "r"(dst), "l"(src));
}
__device__ __forceinline__ void cp_commit() {
    asm volatile("cp.async.commit_group;" ::: "memory");
}
template <int N>
__device__ __forceinline__ void cp_wait() {
    asm volatile("cp.async.wait_group %0;" :: "n"(N) : "memory");
}
__device__ __forceinline__ void ldm_x4(uint32_t* r, uint32_t addr) {
    asm volatile("ldmatrix.sync.aligned.m8n8.x4.shared.b16 {%0,%1,%2,%3}, [%4];"
                 : "=r"(r[0]), "=r"(r[1]), "=r"(r[2]), "=r"(r[3]) : "r"(addr));
}
__device__ __forceinline__ void mma16816(float* d, const uint32_t* a,
                                         const uint32_t* b) {
    asm volatile(
        "mma.sync.aligned.m16n8k16.row.col.f32.bf16.bf16.f32 "
        "{%0,%1,%2,%3}, {%4,%5,%6,%7}, {%8,%9}, {%0,%1,%2,%3};"
        : "+f"(d[0]), "+f"(d[1]), "+f"(d[2]), "+f"(d[3])
        : "r"(a[0]), "r"(a[1]), "r"(a[2]), "r"(a[3]), "r"(b[0]), "r"(b[1]));
}
// Swizzled smem tile offset: rows of 512B (256 bf16), XOR-swizzle inside 128B.
__device__ __forceinline__ uint32_t tile_off(int r, int kbyte) {
    return (uint32_t)(r * 512 + (kbyte & ~127) + ((kbyte & 127) ^ ((r & 7) << 4)));
}

// Order-preserving float->uint transform, round-masked, 12-bit idx packed in.
// Perturbation <= 2048 ulps (~1.2e-4); absorbed by the rescore threshold.
__device__ __forceinline__ uint32_t pack_sc(float s, uint32_t c) {
    uint32_t b = __float_as_uint(s);
    uint32_t u = b ^ ((uint32_t)((int32_t)b >> 31) | 0x80000000u);
    return ((u + 0x800u) & 0xFFFFF000u) | c;
}
__device__ __forceinline__ float unpack_val(uint32_t t) {
    uint32_t u = t & 0xFFFFF000u;
    uint32_t b = (u & 0x80000000u) ? (u ^ 0x80000000u) : ~u;
    return __uint_as_float(b);
}

#define SM_A      0                         // 256 rows * 512B = 128 KB (staging)
#define SM_B(p)   (131072 + (p) * 16384)    // 3 x 16 KB B ring
#define SMEM_TOTAL (131072 + 3 * 16384)     // 176 KB

// ---------------------------------------------------------------------------
// Kernel 1: codebook norms + bf16 conversion. One warp per codebook row.
// ---------------------------------------------------------------------------
__global__ void prep_kernel(const float* __restrict__ E, int K)
{
    int row = (int)((blockIdx.x * blockDim.x + threadIdx.x) >> 5);
    int lane = threadIdx.x & 31;
    if (row >= K) return;
    const float4* p = (const float4*)(E + (size_t)row * DD);
    float4 a = p[lane], b = p[lane + 32];
    float s = a.x*a.x + a.y*a.y + a.z*a.z + a.w*a.w
            + b.x*b.x + b.y*b.y + b.z*b.z + b.w*b.w;
    #pragma unroll
    for (int o = 16; o > 0; o >>= 1) s += __shfl_xor_sync(0xffffffffu, s, o);

    __nv_bfloat162* dst = (__nv_bfloat162*)(g_Ebf + (size_t)row * DD);
    dst[2*lane + 0]      = __float22bfloat162_rn(make_float2(a.x, a.y));
    dst[2*lane + 1]      = __float22bfloat162_rn(make_float2(a.z, a.w));
    dst[2*(lane+32) + 0] = __float22bfloat162_rn(make_float2(b.x, b.y));
    dst[2*(lane+32) + 1] = __float22bfloat162_rn(make_float2(b.z, b.w));

    if (lane == 0) g_C[row] = s;
}

// ---------------------------------------------------------------------------
// Kernel 2: bf16 HMMA GEMM (z @ E^T) + per-token packed top-2 per lane-col.
// R14-proven configuration: K-split grid (1024 CTAs = token tile x slice),
// 8 warps x 32 rows, full A fragments in registers (loaded once), 3-stage
// cp.async B ring with ONE barrier per iteration, packed branch-free top-2.
// ---------------------------------------------------------------------------
__global__ __launch_bounds__(256, 1) void vq_mma_kernel(const float* __restrict__ z)
{
    extern __shared__ char smem[];
    const uint32_t sa = smem_u32(smem);
    const int tid = threadIdx.x;
    const int tile = blockIdx.x >> 2;        // token tile
    const int kh   = blockIdx.x & 3;         // codebook slice
    const int row0 = tile * TM;
    const int code0 = kh * KHC;

    // ---- B tile 0 via cp.async (overlaps with A staging below) ----
    {
        const char* srcB = (const char*)g_Ebf + (size_t)code0 * 512;
        #pragma unroll
        for (int i = 0; i < 4; i++) {          // 32 rows x 32 chunks / 256 thr
            int idx = i * 256 + tid;
            int r = idx >> 5, c = idx & 31;
            cp16(sa + SM_B(0) + tile_off(r, c * 16), srcB + (size_t)r * 512 + c * 16);
        }
        cp_commit();
    }

    // ---- stage A: read fp32 z, convert to bf16 into swizzled smem ----
    {
        const float4* srcZ = (const float4*)(z + (size_t)row0 * DD);
        #pragma unroll
        for (int i = 0; i < 64; i++) {         // 256 rows x 64 float4 / 256 thr
            int idx = i * 256 + tid;
            int r = idx >> 6, c = idx & 63;    // c: float4 index within row
            float4 f = srcZ[(size_t)r * 64 + c];
            __nv_bfloat162 h0 = __float22bfloat162_rn(make_float2(f.x, f.y));
            __nv_bfloat162 h1 = __float22bfloat162_rn(make_float2(f.z, f.w));
            uint2 v = make_uint2(*reinterpret_cast<uint32_t*>(&h0),
                                 *reinterpret_cast<uint32_t*>(&h1));
            *(uint2*)(smem + SM_A + tile_off(r, c * 8)) = v;
        }
    }
    __syncthreads();

    const int l = tid & 31, w = tid >> 5;     // 8 warps, 32 rows each

    // ---- load A fragments into registers (once) ----
    const int a_r  = l & 15;
    const int a_kb = (l >> 4) * 16;
    uint32_t afr[2][16][4];
    #pragma unroll
    for (int mi = 0; mi < 2; mi++)
        #pragma unroll
        for (int ks = 0; ks < 16; ks++)
            ldm_x4(afr[mi][ks],
                   sa + SM_A + tile_off(w * 32 + mi * 16 + a_r, ks * 32 + a_kb));

    uint32_t t0[4], t1[4];                    // packed top-2 per lane-col
    #pragma unroll
    for (int q = 0; q < 4; q++) { t0[q] = 0xFFFFFFFFu; t1[q] = 0xFFFFFFFFu; }

    const int b_r  = ((l >> 4) << 3) + (l & 7);
    const int b_kb = ((l >> 3) & 1) * 16;

    float acc[2][4][4];

    int ridx = 0;                 // ring stage holding tile kb
    for (int kb = 0; kb < NKB; kb++) {
        if (kb < NKB - 1) {   // prefetch next B tile into ring[(ridx+1)%3]
            const char* srcB = (const char*)g_Ebf
                             + (size_t)(code0 + (kb + 1) * TNB) * 512;
            int pidx = (ridx == 2) ? 0 : ridx + 1;
            uint32_t db = sa + SM_B(pidx);
            #pragma unroll
            for (int i = 0; i < 4; i++) {
                int idx = i * 256 + tid;
                int r = idx >> 5, c = idx & 31;
                cp16(db + tile_off(r, c * 16), srcB + (size_t)r * 512 + c * 16);
            }
            cp_commit();
            cp_wait<1>();    // tile kb complete (only kb+1 may remain pending)
        } else {
            cp_wait<0>();
        }
        // Single barrier: tile kb visible; prefetch target (last read kb-2)
        // cannot race any reader (reuse distance 3).
        __syncthreads();

        const uint32_t sB = sa + SM_B(ridx);
        ridx = (ridx == 2) ? 0 : ridx + 1;

        // prefetch C for this tile (latency hidden under the MMA phase)
        float2 Cv[4];
        #pragma unroll
        for (int ni = 0; ni < 4; ni++)
            Cv[ni] = __ldg((const float2*)(g_C + code0 + kb * TNB + ni * 8
                                           + (l & 3) * 2));

        #pragma unroll
        for (int mi = 0; mi < 2; mi++)
            #pragma unroll
            for (int ni = 0; ni < 4; ni++)
                #pragma unroll
                for (int j = 0; j < 4; j++) acc[mi][ni][j] = 0.f;

        #pragma unroll
        for (int ks = 0; ks < 16; ks++) {
            const int k0b = ks * 32;
            uint32_t bfrag[4][2];
            #pragma unroll
            for (int nj = 0; nj < 2; nj++) {
                uint32_t t4[4];
                ldm_x4(t4, sB + tile_off(nj * 16 + b_r, k0b + b_kb));
                bfrag[2*nj][0]   = t4[0]; bfrag[2*nj][1]   = t4[1];
                bfrag[2*nj+1][0] = t4[2]; bfrag[2*nj+1][1] = t4[3];
            }
            #pragma unroll
            for (int mi = 0; mi < 2; mi++)
                #pragma unroll
                for (int ni = 0; ni < 4; ni++)
                    mma16816(acc[mi][ni], afr[mi][ks], bfrag[ni]);
        }

        // ---- epilogue: packed branch-free top-2 (bitonic merges) ----
        const uint32_t cb = (uint32_t)(code0 + kb * TNB + (l & 3) * 2);
        #pragma unroll
        for (int mi = 0; mi < 2; mi++) {
            #pragma unroll
            for (int half = 0; half < 2; half++) {
                const int q = mi * 2 + half;
                uint32_t r0 = t0[q], r1 = t1[q];
                #pragma unroll
                for (int ni = 0; ni < 4; ni++) {
                    float s0 = fmaf(-2.f, acc[mi][ni][half * 2 + 0], Cv[ni].x);
                    float s1 = fmaf(-2.f, acc[mi][ni][half * 2 + 1], Cv[ni].y);
                    uint32_t p0 = pack_sc(s0, cb + (uint32_t)(ni * 8));
                    uint32_t p1 = pack_sc(s1, cb + (uint32_t)(ni * 8) + 1u);
                    uint32_t lo = umin(p0, p1), hi = umax(p0, p1);
                    uint32_t n1 = umin(umax(r0, lo), umin(r1, hi));
                    r0 = umin(r0, lo);
                    r1 = n1;
                }
                t0[q] = r0; t1[q] = r1;
            }
        }
        // no trailing barrier: 3-stage ring gives reuse distance 3
    }

    // write 8 candidates per token into this slice's section (of 32)
    #pragma unroll
    for (int q = 0; q < 4; q++) {
        const int mi = q >> 1, half = q & 1;
        const int r = row0 + w * 32 + mi * 16 + (l >> 2) + half * 8;
        const int base = r * 32 + kh * 8 + (l & 3) * 2;
        g_cv[base]     = unpack_val(t0[q]);
        g_cv[base + 1] = unpack_val(t1[q]);
        g_ci[base]     = (int)(t0[q] & 0xFFFu);
        g_ci[base + 1] = (int)(t1[q] & 0xFFFu);
    }
}

// ---------------------------------------------------------------------------
// Kernel 3: exact rescore of near-tie candidates (reference rounding
// fl(fl(A - 2m) + C), lowest-index tie-break). One warp per token,
// 32 candidates (8 per codebook slice).
// Threshold 4e-4 = bf16 filter noise (1.5e-4) + 2x packing slop (1.2e-4).
// ---------------------------------------------------------------------------
__global__ void rescore_kernel(const float* __restrict__ z,
                               const float* __restrict__ E, int T)
{
    int warp = (int)((blockIdx.x * blockDim.x + threadIdx.x) >> 5);
    int lane = threadIdx.x & 31;
    if (warp >= T) return;
    const size_t t = (size_t)warp;

    float vL = g_cv[t * 32 + lane];
    int   iL = g_ci[t * 32 + lane];
    float v0 = vL;
    #pragma unroll
    for (int o = 16; o > 0; o >>= 1)
        v0 = fminf(v0, __shfl_xor_sync(0xffffffffu, v0, o));
    const float thr = v0 + 4e-4f;
    unsigned mask = __ballot_sync(0xffffffffu, vL <= thr);

    int besti;
    if (__popc(mask) == 1) {
        besti = __shfl_sync(0xffffffffu, iL, __ffs(mask) - 1);
    } else {
        const float4* zp = (const float4*)(z + t * DD);
        float4 z0 = zp[lane], z1 = zp[lane + 32];
        float A = z0.x*z0.x + z0.y*z0.y + z0.z*z0.z + z0.w*z0.w
                + z1.x*z1.x + z1.y*z1.y + z1.z*z1.z + z1.w*z1.w;
        #pragma unroll
        for (int o = 16; o > 0; o >>= 1)
            A += __shfl_xor_sync(0xffffffffu, A, o);

        float bd = CUDART_INF_F; besti = 0x7fffffff;
        #pragma unroll 1
        for (int c = 0; c < 32; c++) {
            if (!((mask >> c) & 1u)) continue;
            int ic = __shfl_sync(0xffffffffu, iL, c);
            const float4* ep = (const float4*)(E + (size_t)ic * DD);
            float4 e0 = ep[lane], e1 = ep[lane + 32];
            float pm = z0.x*e0.x + z0.y*e0.y + z0.z*e0.z + z0.w*e0.w
                     + z1.x*e1.x + z1.y*e1.y + z1.z*e1.z + z1.w*e1.w;
            #pragma unroll
            for (int o = 16; o > 0; o >>= 1)
                pm += __shfl_xor_sync(0xffffffffu, pm, o);
            float d = fmaf(-2.0f, pm, A) + g_C[ic];
            if (d < bd || (d == bd && ic < besti)) { bd = d; besti = ic; }
        }
    }
    if (lane == 0) g_idx[t] = besti;
}

// ---------------------------------------------------------------------------
// Kernel 4: gather quantized rows (float4), write indices, loss partials.
// Per-thread fp32 accumulation (32 terms); block reduction in double.
// ---------------------------------------------------------------------------
__global__ void vq_gather_kernel(const float* __restrict__ z,
                                 const float* __restrict__ E,
                                 float* __restrict__ out,
                                 int T, int with_idx)
{
    __shared__ double sred[256];
    const int tid = threadIdx.x;
    const int cg = tid & 63;       // float4 column group
    const int ro = tid >> 6;       // row offset 0..3
    const int rbase = blockIdx.x * 32;
    const float4* z4 = (const float4*)z;
    const float4* E4 = (const float4*)E;
    float4* out4 = (float4*)out;

    float acc = 0.0f;
    #pragma unroll
    for (int rr = 0; rr < 8; rr++) {
        int row = rbase + rr * 4 + ro;
        int k = g_idx[row];
        float4 e  = __ldg(E4 + (size_t)k * 64 + cg);
        float4 zv = __ldg(z4 + (size_t)row * 64 + cg);
        out4[(size_t)row * 64 + cg] = e;
        float d0 = e.x - zv.x, d1 = e.y - zv.y;
        float d2 = e.z - zv.z, d3 = e.w - zv.w;
        acc = fmaf(d0, d0, acc); acc = fmaf(d1, d1, acc);
        acc = fmaf(d2, d2, acc); acc = fmaf(d3, d3, acc);
        if (with_idx && cg == 0) out[(size_t)T * DD + row] = (float)k;
    }
    sred[tid] = (double)acc;
    __syncthreads();
    #pragma unroll
    for (int o = 128; o > 0; o >>= 1) {
        if (tid < o) sred[tid] += sred[tid + o];
        __syncthreads();
    }
    if (tid == 0) g_part[blockIdx.x] = sred[0];
}

__global__ void vq_loss_kernel(float* __restrict__ out, int T, int npart)
{
    __shared__ double sred[256];
    int tid = threadIdx.x;
    double acc = 0.0;
    for (int i = tid; i < npart; i += 256) acc += g_part[i];
    sred[tid] = acc;
    __syncthreads();
    #pragma unroll
    for (int o = 128; o > 0; o >>= 1) {
        if (tid < o) sred[tid] += sred[tid + o];
        __syncthreads();
    }
    if (tid == 0) {
        float m = (float)(sred[0] / ((double)T * (double)DD));
        out[(size_t)T * DD + T] = m + 0.25f * m;
    }
}

// ---------------------------------------------------------------------------
extern "C" void kernel_launch(void* const* d_in, const int* in_sizes, int n_in,
                              void* d_out, int out_size)
{
    const float* z = (const float*)d_in[0];
    const float* E = (const float*)d_in[1];
    float* out = (float*)d_out;

    int T = in_sizes[0] / DD;   // 65536
    int K = in_sizes[1] / DD;   // 4096

    prep_kernel<<<(K * 32 + 255) / 256, 256>>>(E, K);

    cudaFuncSetAttribute(vq_mma_kernel,
                         cudaFuncAttributeMaxDynamicSharedMemorySize, SMEM_TOTAL);
    vq_mma_kernel<<<(T / TM) * KSPLIT, 256, SMEM_TOTAL>>>(z);

    rescore_kernel<<<T / 8, 256>>>(z, E, T);

    long long need_idx = (long long)T * DD + T;
    int with_idx = (out_size >= need_idx) ? 1 : 0;
    vq_gather_kernel<<<T / 32, 256>>>(z, E, out, T, with_idx);

    if (out_size >= need_idx + 1)
        vq_loss_kernel<<<1, 256>>>(out, T, T / 32);
}